// round 5
// baseline (speedup 1.0000x reference)
#include <cuda_runtime.h>

#define BB   32
#define TT   4096
#define DD   512
#define GG   8
#define OO   512
#define CHUNK 128
#define NCHUNK (TT/CHUNK)   // 32

// Scratch (__device__ globals; no allocations allowed)
__device__ float d_sums[BB*GG*DD];
__device__ int   d_counts[BB*GG];
__device__ int   d_st[TT];      // token ids, group-sorted (shared across b)
__device__ int   d_sg[TT];      // group id per sorted slot

// ---------------------------------------------------------------- prep
// grid=32: every CTA zeros one b's sums slice + counts; CTA 0 additionally
// sorts the (batch-independent) token list by group using warp-aggregated
// atomics (<=8 smem atomics per warp-iteration instead of 32).
__global__ void __launch_bounds__(256) k_prep(const int* __restrict__ tt) {
    int b = blockIdx.x;
    int tid = threadIdx.x;

    // zero this b's sums slice: GG*DD = 4096 floats = 1024 float4
    float4* sz = (float4*)&d_sums[(size_t)b*GG*DD];
    #pragma unroll
    for (int k = 0; k < 4; k++) sz[tid + k*256] = make_float4(0.f,0.f,0.f,0.f);
    if (tid < GG) d_counts[b*GG + tid] = 0;

    if (b != 0) return;

    __shared__ int hist[GG];
    __shared__ int cur[GG];
    if (tid < GG) hist[tid] = 0;
    __syncthreads();

    int lane = tid & 31;

    // histogram pass: one aggregated atomic per distinct group per warp-iter
    for (int t = tid; t < TT; t += 256) {
        int g = tt[t];
        unsigned pm = __match_any_sync(0xffffffffu, g);
        int leader = __ffs(pm) - 1;
        if (lane == leader) atomicAdd(&hist[g], __popc(pm));
    }
    __syncthreads();

    if (tid == 0) {
        int s = 0;
        for (int g = 0; g < GG; g++) { cur[g] = s; s += hist[g]; }
    }
    __syncthreads();

    // scatter pass: leader reserves a block of slots, lanes fan out by rank
    for (int t = tid; t < TT; t += 256) {
        int g = tt[t];
        unsigned pm = __match_any_sync(0xffffffffu, g);
        int leader = __ffs(pm) - 1;
        int rank   = __popc(pm & ((1u << lane) - 1u));
        int base = 0;
        if (lane == leader) base = atomicAdd(&cur[g], __popc(pm));
        base = __shfl_sync(0xffffffffu, base, leader);
        int pos = base + rank;
        d_st[pos] = t;
        d_sg[pos] = g;
    }
}

// ------------------------------------------------------------- masked sums
// grid (NCHUNK, BB), 256 threads. lane = tid&127 owns one float4 of D=512,
// half = tid>>7 strides tokens by 2 -> 64 tokens per thread, 8 macro-steps.
// Token list is group-sorted and shared across b; validity comes from the
// pad mask staged in smem. Loads are warp-uniform predicated (@!P issues no
// transaction) and front-batched 8-wide. Accumulator flushes to d_sums via
// atomicAdd only at group boundaries (<=7 per chunk).
__device__ __forceinline__ void flush_acc(int b, int g, int lane, float4 a) {
    float* dst = &d_sums[((size_t)b*GG + g)*DD + lane*4];
    atomicAdd(dst+0, a.x); atomicAdd(dst+1, a.y);
    atomicAdd(dst+2, a.z); atomicAdd(dst+3, a.w);
}

__global__ void __launch_bounds__(256) k_main(const float* __restrict__ batch,
                                              const int* __restrict__ pad) {
    __shared__ int s_tok[CHUNK];
    __shared__ int s_grp[CHUNK];
    __shared__ int s_val[CHUNK];

    int b   = blockIdx.y;
    int c0  = blockIdx.x * CHUNK;
    int tid = threadIdx.x;

    if (tid < CHUNK) {
        int t = d_st[c0 + tid];
        s_tok[tid] = t;
        s_grp[tid] = d_sg[c0 + tid];
        s_val[tid] = pad[(size_t)b*TT + t] ? 0 : 1;   // bool -> int32 transport
    }
    __syncthreads();

    // per-(b,g) valid counts: 64 threads, 16 smem reads each
    if (tid < 64) {
        int g = tid >> 3, j = tid & 7;
        int c = 0;
        #pragma unroll
        for (int k = 0; k < 16; k++) {
            int i = j*16 + k;
            c += (s_grp[i] == g) & s_val[i];
        }
        if (c) atomicAdd(&d_counts[b*GG + g], c);
    }

    int lane = tid & 127;
    int half = tid >> 7;
    const float4* bb = (const float4*)(batch + (size_t)b * TT * DD);

    float4 acc = make_float4(0.f,0.f,0.f,0.f);
    int curg = s_grp[0];

    #define PLOAD(V, J)                                                     \
        float4 V = make_float4(0.f,0.f,0.f,0.f);                            \
        if (s_val[i + 2*(J)])                                               \
            V = __ldcs(&bb[(size_t)s_tok[i + 2*(J)] * (DD/4) + lane]);

    #define ACCSTEP(J, V)                                                   \
        { int g_ = s_grp[i + 2*(J)];                                        \
          if (g_ != curg) {                                                 \
              flush_acc(b, curg, lane, acc);                                \
              acc = make_float4(0.f,0.f,0.f,0.f); curg = g_; }              \
          acc.x += (V).x; acc.y += (V).y; acc.z += (V).z; acc.w += (V).w; }

    #pragma unroll
    for (int s = 0; s < 8; s++) {
        int i = half + s*16;
        PLOAD(v0, 0) PLOAD(v1, 1) PLOAD(v2, 2) PLOAD(v3, 3)
        PLOAD(v4, 4) PLOAD(v5, 5) PLOAD(v6, 6) PLOAD(v7, 7)
        ACCSTEP(0, v0); ACCSTEP(1, v1); ACCSTEP(2, v2); ACCSTEP(3, v3);
        ACCSTEP(4, v4); ACCSTEP(5, v5); ACCSTEP(6, v6); ACCSTEP(7, v7);
    }
    flush_acc(b, curg, lane, acc);
    #undef PLOAD
    #undef ACCSTEP
}

// ------------------------------------------------------ means -> GEMM + bias
// grid (G, OO/128, BB/8), 256 threads. Tile: 8 b-rows x 128 outputs.
// Thread = 1 b-row x 4 outputs; mean reads are warp-broadcast.
#define GBH  8
#define GOCH 128
#define GDT  16

__global__ void __launch_bounds__(256) k_gemm(const float* __restrict__ W,
                                              const float* __restrict__ bias,
                                              float* __restrict__ out) {
    __shared__ float s_mean[GBH * DD];      // 16 KB
    __shared__ float s_w[GDT * GOCH];       //  8 KB

    int g   = blockIdx.x;
    int o0  = blockIdx.y * GOCH;
    int b0  = blockIdx.z * GBH;
    int tid = threadIdx.x;

    for (int idx = tid; idx < GBH*DD; idx += 256) {
        int bl = idx >> 9;
        int d  = idx & (DD-1);
        int bg = (b0 + bl)*GG + g;
        int c  = d_counts[bg];
        float s = d_sums[(size_t)bg*DD + d];
        s_mean[bl*DD + d] = (c > 0) ? s / (float)c : 0.0f;
    }

    int oq   = tid & 31;
    int brow = tid >> 5;
    float a0=0.f, a1=0.f, a2=0.f, a3=0.f;

    for (int d0 = 0; d0 < DD; d0 += GDT) {
        __syncthreads();
        #pragma unroll
        for (int k = 0; k < 2; k++) {
            int idx = tid + k*256;
            int dd  = idx >> 5;
            int o4  = idx & 31;
            ((float4*)s_w)[idx] =
                *((const float4*)(W + ((size_t)(g*DD + d0 + dd))*OO + o0) + o4);
        }
        __syncthreads();

        #pragma unroll
        for (int dd = 0; dd < GDT; dd++) {
            float4 w = ((const float4*)s_w)[dd*32 + oq];
            float  m = s_mean[brow*DD + d0 + dd];
            a0 += m*w.x; a1 += m*w.y; a2 += m*w.z; a3 += m*w.w;
        }
    }

    int o = o0 + oq*4;
    float4 bv = *(const float4*)(bias + (size_t)g*OO + o);
    float4 r = make_float4(a0+bv.x, a1+bv.y, a2+bv.z, a3+bv.w);
    *(float4*)(out + ((size_t)((b0 + brow)*GG + g))*OO + o) = r;
}

// ---------------------------------------------------------------- launcher
// metadata order: batch(f32), W(f32), b_bias(f32), token_types(i32),
//                 key_padding_mask(bool -> int32)
extern "C" void kernel_launch(void* const* d_in, const int* in_sizes, int n_in,
                              void* d_out, int out_size) {
    const float* batch = (const float*)d_in[0];
    const float* W     = (const float*)d_in[1];
    const float* bias  = (const float*)d_in[2];
    const int*   tt    = (const int*)d_in[3];
    const int*   pad   = (const int*)d_in[4];
    float* out = (float*)d_out;

    k_prep<<<BB, 256>>>(tt);

    dim3 gmain(NCHUNK, BB);
    k_main<<<gmain, 256>>>(batch, pad);

    dim3 ggemm(GG, OO/GOCH, BB/GBH);
    k_gemm<<<ggemm, 256>>>(W, bias, out);
}